// round 13
// baseline (speedup 1.0000x reference)
#include <cuda_runtime.h>
#include <cuda_fp16.h>
#include <cstdint>
#include <math.h>

#define NB 2
#define NT 2048
#define ND 1024
#define NH 16
#define NBT (NB*NT)
#define NCHUNK (ND/32)     // 32 chunks of BK=32
#define QSCALE 0.18033688011111772f   // 0.125 * log2(e)

// counters
#define C_ROPE 0
#define C_R    1
#define C_FOLD 2
#define C_PA   3
#define C_WQ   4
#define C_WK   5
#define C_WO   6
#define C_WV   7
#define C_QKV  8    // +nt (24 n-tiles, target 32 each)
#define C_FL   32   // +mt (32 (b,qt) groups, target 16 each)

// ---------------- scratch ---------------------------------------------------
__device__ __half g_A[(size_t)NBT*ND];          // fp16 x
__device__ __half g_O16[(size_t)NBT*ND];        // fp16 attention output
__device__ __half g_W[(size_t)3*ND*ND];         // [n,k] fp16 Wq|Wk|Wv'
__device__ __half g_WoH[(size_t)ND*ND];         // [n,k] fp16 Wo
__device__ float g_rope[(size_t)NT*64];
__device__ float g_R[64*64];
__device__ float g_Wvp[(size_t)ND*ND];
__device__ __half g_Qs[(size_t)NBT*ND];
__device__ __half g_Ks[(size_t)NBT*ND];
__device__ __half g_Vs[(size_t)NBT*ND];
__device__ int g_sync[64];

// ---------------- helpers ---------------------------------------------------
__device__ __forceinline__ uint32_t smem_u32(const void* p) {
    uint32_t a;
    asm("{ .reg .u64 t; cvta.to.shared.u64 t, %1; cvt.u32.u64 %0, t; }"
        : "=r"(a) : "l"(p));
    return a;
}
__device__ __forceinline__ float ex2(float x) {
    float r;
    asm("ex2.approx.ftz.f32 %0, %1;" : "=f"(r) : "f"(x));
    return r;
}
#define CPA16(s, g) asm volatile("cp.async.cg.shared.global [%0], [%1], 16;\n" :: "r"(s), "l"(g))
#define CPCOMMIT()  asm volatile("cp.async.commit_group;\n" ::: "memory")
#define CPWAIT0()   asm volatile("cp.async.wait_group 0;\n" ::: "memory")
#define CPWAIT1()   asm volatile("cp.async.wait_group 1;\n" ::: "memory")

#define LDSM4(r, addr)                                                        \
    asm volatile("ldmatrix.sync.aligned.m8n8.x4.shared.b16 {%0,%1,%2,%3}, [%4];" \
                 : "=r"((r)[0]), "=r"((r)[1]), "=r"((r)[2]), "=r"((r)[3])     \
                 : "r"(addr))
#define LDSM4T(r, addr)                                                       \
    asm volatile("ldmatrix.sync.aligned.m8n8.x4.trans.shared.b16 {%0,%1,%2,%3}, [%4];" \
                 : "=r"((r)[0]), "=r"((r)[1]), "=r"((r)[2]), "=r"((r)[3])     \
                 : "r"(addr))
#define MMA_F16(d, a, b)                                                      \
    asm volatile("mma.sync.aligned.m16n8k16.row.col.f32.f16.f16.f32 "         \
                 "{%0,%1,%2,%3},{%4,%5,%6,%7},{%8,%9},{%0,%1,%2,%3};"         \
                 : "+f"((d)[0]), "+f"((d)[1]), "+f"((d)[2]), "+f"((d)[3])     \
                 : "r"((a)[0]), "r"((a)[1]), "r"((a)[2]), "r"((a)[3]),        \
                   "r"((b)[0]), "r"((b)[1]))

__device__ __forceinline__ uint32_t pack_f16(float lo, float hi) {
    uint32_t r;
    asm("cvt.rn.f16x2.f32 %0, %1, %2;" : "=r"(r) : "f"(hi), "f"(lo));
    return r;
}

// ---- sync primitives --------------------------------------------------------
__device__ __forceinline__ void waitcnt(int idx, int target) {
    if (threadIdx.x == 0) {
        while (atomicAdd(&g_sync[idx], 0) < target)
            asm volatile("nanosleep.u32 200;");
    }
    __syncthreads();
}
__device__ __forceinline__ void donecnt(int idx) {
    __threadfence();
    __syncthreads();
    if (threadIdx.x == 0) atomicAdd(&g_sync[idx], 1);
}

// ---------------- prep jobs (noinline: isolate register allocation) ---------
__device__ __noinline__ void job_rope(int j) {
    int base = j * 8192;
    for (int it = 0; it < 64; it++) {
        int g = base + it * 128 + threadIdx.x;
        int s = g >> 6, i = g & 63, k = i & 31;
        double inv = exp(-(double)k * (log(10000.0) / 32.0));
        double ph = fmod((double)s * inv, 6.283185307179586);
        float phf = (float)ph;
        g_rope[g] = (i < 32) ? cosf(phf) : sinf(phf);
    }
}
__device__ __noinline__ void job_R(int i, char* smemc) {
    float* red = (float*)smemc;
    const int tid = threadIdx.x;
    int jj = tid & 63, half = tid >> 6;
    float acc = 0.f;
    for (int s = half; s < NT; s += 2)
        acc += g_rope[s * 64 + i] * g_rope[s * 64 + jj];
    if (half) red[jj] = acc;
    __syncthreads();
    if (!half) g_R[i * 64 + jj] = acc + red[jj];
}
__device__ __noinline__ void job_fold(const float* __restrict__ Wv, int d0, char* smemc) {
    float* Rs = (float*)smemc;       // 4096 floats
    float* wr = Rs + 4096;           // 1024 floats
    const int tid = threadIdx.x;
    for (int it = tid; it < 4096; it += 128) Rs[it] = g_R[it];
    for (int dd = 0; dd < 8; dd++) {
        int d = d0 + dd;
        __syncthreads();
        for (int it = tid; it < 1024; it += 128)
            wr[it] = Wv[(size_t)d * ND + it];
        __syncthreads();
#pragma unroll
        for (int jb = 0; jb < 8; jb++) {
            int col = jb * 128 + tid;
            int hh = col >> 6, jx = col & 63;
            float acc = 0.f;
#pragma unroll 8
            for (int i = 0; i < 64; i++)
                acc += wr[hh * 64 + i] * Rs[i * 64 + jx];
            g_Wvp[(size_t)d * ND + col] = acc;
        }
    }
}
__device__ __noinline__ void job_prepa(const float* __restrict__ x, int r0) {
    const float4* src = (const float4*)x + (size_t)r0 * 256;
    uint2* dst = (uint2*)g_A + (size_t)r0 * 256;
    const int tid = threadIdx.x;
    for (int it = 0; it < 64; it++) {
        int g = it * 128 + tid;
        float4 v = src[g];
        uint2 o2;
        o2.x = pack_f16(v.x, v.y);
        o2.y = pack_f16(v.z, v.w);
        dst[g] = o2;
    }
}
__device__ __noinline__ void transpose_band(const float* __restrict__ W,
                                            __half* __restrict__ dst,
                                            int k0, char* smemc) {
    float* t = (float*)smemc;   // 32*33 floats
    const int tx = threadIdx.x & 31, ty = threadIdx.x >> 5;
    for (int n0 = 0; n0 < ND; n0 += 32) {
        __syncthreads();
#pragma unroll
        for (int i = ty; i < 32; i += 4)
            t[i * 33 + tx] = W[(size_t)(k0 + i) * ND + n0 + tx];
        __syncthreads();
#pragma unroll
        for (int i = ty; i < 32; i += 4)
            dst[(size_t)(n0 + i) * ND + k0 + tx] = __float2half(t[tx * 33 + i]);
    }
}

// ---------------- HMMA GEMM tile: 128x128x32, 4 warps (2x2 of 64x64) --------
#define GST 10240

__device__ __noinline__ void gemm_tile(
    const __half* __restrict__ A, const __half* __restrict__ B,
    float* __restrict__ C, const float* __restrict__ bias,
    int m0, int n0, int Ncols, int epi, char* smemc)
{
    const uint32_t sbase = smem_u32(smemc);
    const int tid = threadIdx.x, lane = tid & 31, wid = tid >> 5;
    const int wm = wid >> 1, wn = wid & 1;
    const __half* Ap = A + (size_t)m0 * ND;
    const __half* Bp = B + (size_t)n0 * ND;

#define G_LOAD(st, ch)                                                        \
    do {                                                                      \
        uint32_t _sA = sbase + (st) * GST;                                    \
        uint32_t _sB = sbase + 3 * GST + (st) * GST;                          \
        const __half* _ag = Ap + (ch) * 32;                                   \
        const __half* _bg = Bp + (ch) * 32;                                   \
        _Pragma("unroll")                                                     \
        for (int _i = 0; _i < 4; _i++) {                                      \
            int _idx = _i * 128 + tid;                                        \
            int _r = _idx >> 2, _sg = _idx & 3;                               \
            uint32_t _o = (uint32_t)(_r * 80 + _sg * 16);                     \
            CPA16(_sA + _o, _ag + (size_t)_r * ND + _sg * 8);                 \
            CPA16(_sB + _o, _bg + (size_t)_r * ND + _sg * 8);                 \
        }                                                                     \
        CPCOMMIT();                                                           \
    } while (0)

    float acc[4][8][4];
#pragma unroll
    for (int i = 0; i < 4; i++)
#pragma unroll
        for (int jx = 0; jx < 8; jx++)
#pragma unroll
            for (int k = 0; k < 4; k++) acc[i][jx][k] = 0.f;

    G_LOAD(0, 0);
    G_LOAD(1, 1);

    for (int c = 0; c < NCHUNK; c++) {
        if (c < NCHUNK - 1) CPWAIT1(); else CPWAIT0();
        __syncthreads();
        if (c + 2 < NCHUNK) G_LOAD((c + 2) % 3, c + 2);

        int st = c % 3;
        uint32_t sA = sbase + st * GST;
        uint32_t sB = sbase + 3 * GST + st * GST;
#pragma unroll
        for (int kk = 0; kk < 2; kk++) {
            uint32_t a[4][4], b[8][2];
#pragma unroll
            for (int mi = 0; mi < 4; mi++) {
                uint32_t ad = sA + (uint32_t)((wm * 64 + mi * 16 + (lane & 15)) * 80
                                              + kk * 32 + (lane >> 4) * 16);
                LDSM4(a[mi], ad);
            }
#pragma unroll
            for (int pr = 0; pr < 4; pr++) {
                uint32_t t4[4];
                uint32_t bd = sB + (uint32_t)((wn * 64 + pr * 16 + ((lane >> 4) & 1) * 8
                                               + (lane & 7)) * 80
                                              + kk * 32 + ((lane >> 3) & 1) * 16);
                LDSM4(t4, bd);
                b[2 * pr][0] = t4[0]; b[2 * pr][1] = t4[1];
                b[2 * pr + 1][0] = t4[2]; b[2 * pr + 1][1] = t4[3];
            }
#pragma unroll
            for (int mi = 0; mi < 4; mi++)
#pragma unroll
                for (int ni = 0; ni < 8; ni++)
                    MMA_F16(acc[mi][ni], a[mi], b[ni]);
        }
    }
    __syncthreads();

    if (epi == 2) {
        const int arr = n0 >> 10;
        __half* hb = (arr == 0) ? g_Qs : (arr == 1) ? g_Ks : g_Vs;
        const float sc = (arr == 0) ? QSCALE : 1.f;
#pragma unroll
        for (int mi = 0; mi < 4; mi++)
#pragma unroll
            for (int ni = 0; ni < 8; ni++) {
                int row = m0 + wm * 64 + mi * 16 + (lane >> 2);
                int cc = (n0 & 1023) + wn * 64 + ni * 8 + (lane & 3) * 2;
                size_t di = (size_t)row * ND + cc;
                *(uint32_t*)&hb[di] = pack_f16(acc[mi][ni][0] * sc, acc[mi][ni][1] * sc);
                *(uint32_t*)&hb[di + (size_t)8 * ND] =
                    pack_f16(acc[mi][ni][2] * sc, acc[mi][ni][3] * sc);
            }
    } else {
#pragma unroll
        for (int mi = 0; mi < 4; mi++)
#pragma unroll
            for (int ni = 0; ni < 8; ni++) {
                int row = m0 + wm * 64 + mi * 16 + (lane >> 2);
                int col = n0 + wn * 64 + ni * 8 + (lane & 3) * 2;
                float b0 = bias[col], b1 = bias[col + 1];
                float2 v0 = { acc[mi][ni][0] + b0, acc[mi][ni][1] + b1 };
                float2 v1 = { acc[mi][ni][2] + b0, acc[mi][ni][3] + b1 };
                *(float2*)&C[(size_t)row * Ncols + col] = v0;
                *(float2*)&C[(size_t)(row + 8) * Ncols + col] = v1;
            }
    }
#undef G_LOAD
}

// ---------------- flash tile: Br=128 (4 warps), Bc=64, hd=64 ----------------
#define FQB   18432
#define FKVB  9216

__device__ __noinline__ void flash_tile(int qt, int b, int h, char* smemc)
{
    const uint32_t sbase = smem_u32(smemc);
    const uint32_t sQ = sbase;
    const uint32_t sKV0 = sbase + FQB;

    const int tid = threadIdx.x, lane = tid & 31, wid = tid >> 5;
    const int q0 = qt * 128;
    const int wq = wid * 32;
    const size_t base = ((size_t)b * NT) * ND + (size_t)h * 64;

    const __half* gs[2] = { g_Ks + base, g_Vs + base };

#define KV_LOAD(stg, kv0)                                                     \
    do {                                                                      \
        uint32_t _sd = sKV0 + (stg) * (2 * FKVB);                             \
        _Pragma("unroll")                                                     \
        for (int _i = 0; _i < 8; _i++) {                                      \
            int _idx = _i * 128 + tid;                                        \
            int _arr = _idx >> 9, _rem = _idx & 511;                          \
            int _r = _rem >> 3, _sg = _rem & 7;                               \
            CPA16(_sd + (uint32_t)(_arr * FKVB + _r * 144 + _sg * 16),        \
                  gs[_arr] + (size_t)((kv0) + _r) * ND + _sg * 8);            \
        }                                                                     \
        CPCOMMIT();                                                           \
    } while (0)

    {
        const __half* qp = g_Qs + base;
#pragma unroll
        for (int i = 0; i < 8; i++) {
            int idx = i * 128 + tid;
            int r = idx >> 3, sg = idx & 7;
            CPA16(sQ + (uint32_t)(r * 144 + sg * 16),
                  qp + (size_t)(q0 + r) * ND + sg * 8);
        }
    }
    KV_LOAD(0, 0);
    KV_LOAD(1, 64);

    CPWAIT1();
    __syncthreads();
    uint32_t aq[4][2][4];
#pragma unroll
    for (int kk = 0; kk < 4; kk++)
#pragma unroll
        for (int mi = 0; mi < 2; mi++) {
            uint32_t off = (uint32_t)((wq + mi * 16 + (lane & 15)) * 144
                                      + kk * 32 + (lane >> 4) * 16);
            LDSM4(aq[kk][mi], sQ + off);
        }

    float o[2][8][4];
    float mrow[2][2], lrow[2][2];
#pragma unroll
    for (int mi = 0; mi < 2; mi++) {
        mrow[mi][0] = mrow[mi][1] = -1e30f;
        lrow[mi][0] = lrow[mi][1] = 0.f;
#pragma unroll
        for (int nd = 0; nd < 8; nd++)
#pragma unroll
            for (int k = 0; k < 4; k++) o[mi][nd][k] = 0.f;
    }

    for (int t = 0; t < NT / 64; t++) {
        if (t < NT / 64 - 1) CPWAIT1(); else CPWAIT0();
        __syncthreads();
        const uint32_t sK = sKV0 + (t & 1) * (2 * FKVB);
        const uint32_t sV = sK + FKVB;

        float s[2][8][4];
#pragma unroll
        for (int mi = 0; mi < 2; mi++)
#pragma unroll
            for (int ni = 0; ni < 8; ni++)
#pragma unroll
                for (int k = 0; k < 4; k++) s[mi][ni][k] = 0.f;

#pragma unroll
        for (int kk = 0; kk < 4; kk++) {
            uint32_t bk[8][2];
#pragma unroll
            for (int pr = 0; pr < 4; pr++) {
                uint32_t off = (uint32_t)((pr * 16 + ((lane >> 4) & 1) * 8 + (lane & 7)) * 144
                                          + kk * 32 + ((lane >> 3) & 1) * 16);
                uint32_t t4[4];
                LDSM4(t4, sK + off);
                bk[2 * pr][0] = t4[0]; bk[2 * pr][1] = t4[1];
                bk[2 * pr + 1][0] = t4[2]; bk[2 * pr + 1][1] = t4[3];
            }
#pragma unroll
            for (int mi = 0; mi < 2; mi++)
#pragma unroll
                for (int ni = 0; ni < 8; ni++)
                    MMA_F16(s[mi][ni], aq[kk][mi], bk[ni]);
        }

#pragma unroll
        for (int mi = 0; mi < 2; mi++)
#pragma unroll
            for (int hf = 0; hf < 2; hf++) {
                float vmax = -1e30f;
#pragma unroll
                for (int ni = 0; ni < 8; ni++)
                    vmax = fmaxf(vmax, fmaxf(s[mi][ni][2 * hf], s[mi][ni][2 * hf + 1]));
                vmax = fmaxf(vmax, __shfl_xor_sync(0xffffffffu, vmax, 1));
                vmax = fmaxf(vmax, __shfl_xor_sync(0xffffffffu, vmax, 2));
                float mo = mrow[mi][hf];
                float mn = fmaxf(mo, vmax);
                float corr = ex2(mo - mn);
                mrow[mi][hf] = mn;
                float rs = 0.f;
#pragma unroll
                for (int ni = 0; ni < 8; ni++) {
                    float p0 = ex2(s[mi][ni][2 * hf] - mn);
                    float p1 = ex2(s[mi][ni][2 * hf + 1] - mn);
                    s[mi][ni][2 * hf] = p0;
                    s[mi][ni][2 * hf + 1] = p1;
                    rs += p0 + p1;
                }
                rs += __shfl_xor_sync(0xffffffffu, rs, 1);
                rs += __shfl_xor_sync(0xffffffffu, rs, 2);
                lrow[mi][hf] = lrow[mi][hf] * corr + rs;
#pragma unroll
                for (int ni = 0; ni < 8; ni++) {
                    o[mi][ni][2 * hf] *= corr;
                    o[mi][ni][2 * hf + 1] *= corr;
                }
            }

#pragma unroll
        for (int kk = 0; kk < 4; kk++) {
            uint32_t bv[8][2];
#pragma unroll
            for (int q = 0; q < 4; q++) {
                uint32_t off = (uint32_t)((kk * 16 + ((lane >> 3) & 1) * 8 + (lane & 7)) * 144
                                          + q * 32 + ((lane >> 4) & 1) * 16);
                uint32_t t4[4];
                LDSM4T(t4, sV + off);
                bv[2 * q][0] = t4[0]; bv[2 * q][1] = t4[1];
                bv[2 * q + 1][0] = t4[2]; bv[2 * q + 1][1] = t4[3];
            }
#pragma unroll
            for (int mi = 0; mi < 2; mi++) {
                const float* p0 = s[mi][2 * kk];
                const float* p1 = s[mi][2 * kk + 1];
                uint32_t ap[4];
                ap[0] = pack_f16(p0[0], p0[1]);
                ap[1] = pack_f16(p0[2], p0[3]);
                ap[2] = pack_f16(p1[0], p1[1]);
                ap[3] = pack_f16(p1[2], p1[3]);
#pragma unroll
                for (int nd = 0; nd < 8; nd++)
                    MMA_F16(o[mi][nd], ap, bv[nd]);
            }
        }

        if (t + 2 < NT / 64) {
            __syncthreads();
            KV_LOAD(t & 1, (t + 2) * 64);
        }
    }

#pragma unroll
    for (int mi = 0; mi < 2; mi++)
#pragma unroll
        for (int hf = 0; hf < 2; hf++) {
            float inv = 1.f / lrow[mi][hf];
            int m = b * NT + q0 + wq + mi * 16 + (lane >> 2) + hf * 8;
#pragma unroll
            for (int nd = 0; nd < 8; nd++) {
                int k = h * 64 + nd * 8 + (lane & 3) * 2;
                *(uint32_t*)&g_O16[(size_t)m * ND + k] =
                    pack_f16(o[mi][nd][2 * hf] * inv, o[mi][nd][2 * hf + 1] * inv);
            }
        }
#undef KV_LOAD
}

// ---------------- fused kernel: prep -> QKV -> flash -> out-proj ------------
// bid layout: [0,16) rope | [16,80) R | [80,208) fold | [208,336) prep_a
//             [336,432) transpose Wq/Wk/Wo | [432,464) transpose Wv'
//             [464,1232) QKV | [1232,1744) flash | [1744,2000) out-proj
__global__ __launch_bounds__(128, 2)
void fused(const float* __restrict__ x, const float* __restrict__ Wq,
           const float* __restrict__ Wk, const float* __restrict__ Wv,
           const float* __restrict__ Wo, const float* __restrict__ bo,
           float* __restrict__ out)
{
    extern __shared__ char smemc[];
    const int bid = blockIdx.x;

    if (bid < 16) {
        job_rope(bid);
        donecnt(C_ROPE);
    } else if (bid < 80) {
        waitcnt(C_ROPE, 16);
        job_R(bid - 16, smemc);
        donecnt(C_R);
    } else if (bid < 208) {
        waitcnt(C_R, 64);
        job_fold(Wv, (bid - 80) * 8, smemc);
        donecnt(C_FOLD);
    } else if (bid < 336) {
        job_prepa(x, (bid - 208) * 32);
        donecnt(C_PA);
    } else if (bid < 432) {
        int l = bid - 336, cls = l >> 5, band = l & 31;
        const float* W = (cls == 0) ? Wq : (cls == 1) ? Wk : Wo;
        __half* dst = (cls == 0) ? g_W
                    : (cls == 1) ? (g_W + (size_t)ND * ND) : g_WoH;
        transpose_band(W, dst, band * 32, smemc);
        donecnt(cls == 0 ? C_WQ : cls == 1 ? C_WK : C_WO);
    } else if (bid < 464) {
        waitcnt(C_FOLD, 128);
        transpose_band(g_Wvp, g_W + (size_t)2 * ND * ND, (bid - 432) * 32, smemc);
        donecnt(C_WV);
    } else if (bid < 1232) {
        // QKV gemm tiles, grouped by head-pair; kinds: 0=K, 1=V, 2=Q
        int l = bid - 464, hp = l / 96, w = l % 96, kind = w >> 5, m = w & 31;
        int nt = (kind == 0) ? 8 + hp : (kind == 1) ? 16 + hp : hp;
        waitcnt(C_PA, 128);
        waitcnt(kind == 0 ? C_WK : kind == 1 ? C_WV : C_WQ, 32);
        gemm_tile(g_A, g_W, nullptr, nullptr, m * 128, nt * 128, 0, 2, smemc);
        donecnt(C_QKV + nt);
    } else if (bid < 1744) {
        int l = bid - 1232, hp = l >> 6, w = l & 63;
        int h = hp * 2 + (w >> 5), b = (w >> 4) & 1, qt = w & 15;
        waitcnt(C_QKV + hp, 32);
        waitcnt(C_QKV + 8 + hp, 32);
        waitcnt(C_QKV + 16 + hp, 32);
        flash_tile(qt, b, h, smemc);
        donecnt(C_FL + b * 16 + qt);
    } else {
        int l = bid - 1744, mt = l >> 3, ntc = l & 7;
        waitcnt(C_WO, 32);
        waitcnt(C_FL + mt, 16);
        gemm_tile(g_O16, g_WoH, out, bo, mt * 128, ntc * 128, ND, 1, smemc);
    }
}

// ---------------- host launcher --------------------------------------------
extern "C" void kernel_launch(void* const* d_in, const int* in_sizes, int n_in,
                              void* d_out, int out_size) {
    (void)in_sizes; (void)n_in; (void)out_size;
    const float* x  = (const float*)d_in[0];
    const float* Wq = (const float*)d_in[1];
    const float* Wk = (const float*)d_in[2];
    const float* Wv = (const float*)d_in[3];
    const float* Wo = (const float*)d_in[4];
    const float* bo = (const float*)d_in[5];
    float* out = (float*)d_out;

    int* syncp;
    cudaGetSymbolAddress((void**)&syncp, g_sync);
    cudaMemsetAsync(syncp, 0, sizeof(int) * 64, 0);

    cudaFuncSetAttribute(fused, cudaFuncAttributeMaxDynamicSharedMemorySize, 61440);
    fused<<<2000, 128, 61440>>>(x, Wq, Wk, Wv, Wo, bo, out);
}

// round 14
// speedup vs baseline: 1.3311x; 1.3311x over previous
#include <cuda_runtime.h>
#include <cuda_fp16.h>
#include <cstdint>
#include <math.h>

#define NB 2
#define NT 2048
#define ND 1024
#define NH 16
#define NBT (NB*NT)
#define NCHUNK (ND/32)     // 32 chunks of BK=32
#define QSCALE 0.18033688011111772f   // 0.125 * log2(e)

// counters: [0..47] QKV (nt*2 + half, target 16), [48..79] flash (b*16+qt, target 16)
#define C_FL   48

// ---------------- scratch ---------------------------------------------------
__device__ __half g_A[(size_t)NBT*ND];          // fp16 x
__device__ __half g_O16[(size_t)NBT*ND];        // fp16 attention output
__device__ __half g_W[(size_t)3*ND*ND];         // [n,k] fp16 Wq|Wk|Wv'
__device__ __half g_WoH[(size_t)ND*ND];         // [n,k] fp16 Wo
__device__ float g_R[64*64];
__device__ float g_Wvp[(size_t)ND*ND];
__device__ __half g_Qs[(size_t)NBT*ND];
__device__ __half g_Ks[(size_t)NBT*ND];
__device__ __half g_Vs[(size_t)NBT*ND];
__device__ int g_sync[96];

// ---------------- helpers ---------------------------------------------------
__device__ __forceinline__ uint32_t smem_u32(const void* p) {
    uint32_t a;
    asm("{ .reg .u64 t; cvta.to.shared.u64 t, %1; cvt.u32.u64 %0, t; }"
        : "=r"(a) : "l"(p));
    return a;
}
__device__ __forceinline__ float ex2(float x) {
    float r;
    asm("ex2.approx.ftz.f32 %0, %1;" : "=f"(r) : "f"(x));
    return r;
}
#define CPA16(s, g) asm volatile("cp.async.cg.shared.global [%0], [%1], 16;\n" :: "r"(s), "l"(g))
#define CPCOMMIT()  asm volatile("cp.async.commit_group;\n" ::: "memory")
#define CPWAIT0()   asm volatile("cp.async.wait_group 0;\n" ::: "memory")
#define CPWAIT1()   asm volatile("cp.async.wait_group 1;\n" ::: "memory")

#define LDSM4(r, addr)                                                        \
    asm volatile("ldmatrix.sync.aligned.m8n8.x4.shared.b16 {%0,%1,%2,%3}, [%4];" \
                 : "=r"((r)[0]), "=r"((r)[1]), "=r"((r)[2]), "=r"((r)[3])     \
                 : "r"(addr))
#define LDSM4T(r, addr)                                                       \
    asm volatile("ldmatrix.sync.aligned.m8n8.x4.trans.shared.b16 {%0,%1,%2,%3}, [%4];" \
                 : "=r"((r)[0]), "=r"((r)[1]), "=r"((r)[2]), "=r"((r)[3])     \
                 : "r"(addr))
#define MMA_F16(d, a, b)                                                      \
    asm volatile("mma.sync.aligned.m16n8k16.row.col.f32.f16.f16.f32 "         \
                 "{%0,%1,%2,%3},{%4,%5,%6,%7},{%8,%9},{%0,%1,%2,%3};"         \
                 : "+f"((d)[0]), "+f"((d)[1]), "+f"((d)[2]), "+f"((d)[3])     \
                 : "r"((a)[0]), "r"((a)[1]), "r"((a)[2]), "r"((a)[3]),        \
                   "r"((b)[0]), "r"((b)[1]))

__device__ __forceinline__ uint32_t pack_f16(float lo, float hi) {
    uint32_t r;
    asm("cvt.rn.f16x2.f32 %0, %1, %2;" : "=r"(r) : "f"(hi), "f"(lo));
    return r;
}

// ---- sync primitives --------------------------------------------------------
__device__ __forceinline__ void waitcnt(int idx, int target) {
    if (threadIdx.x == 0) {
        while (atomicAdd(&g_sync[idx], 0) < target)
            asm volatile("nanosleep.u32 200;");
    }
    __syncthreads();
}
__device__ __forceinline__ void donecnt(int idx) {
    __threadfence();
    __syncthreads();
    if (threadIdx.x == 0) atomicAdd(&g_sync[idx], 1);
}

// ---------------- prep kernels (separate launches) ---------------------------
// R[i][j] = sum_{s=0}^{N-1} rope[s,i] rope[s,j] in closed form (Dirichlet sums)
__device__ __forceinline__ void trig_sums(double th, double& C, double& S) {
    // C = sum cos(s*th), S = sum sin(s*th), s = 0..2047
    if (th == 0.0) { C = 2048.0; S = 0.0; return; }
    double q = sin(1024.0 * th) / sin(0.5 * th);
    C = q * cos(1023.5 * th);
    S = q * sin(1023.5 * th);
}
__global__ void compute_R_closed() {
    int g = blockIdx.x * blockDim.x + threadIdx.x;   // 4096
    int i = g >> 6, j = g & 63;
    double a = exp(-(double)(i & 31) * (log(10000.0) / 32.0));
    double b = exp(-(double)(j & 31) * (log(10000.0) / 32.0));
    double th1 = ((i & 31) == (j & 31)) ? 0.0 : (a - b);
    double th2 = a + b;
    double C1, S1, C2, S2;
    trig_sums(th1, C1, S1);
    trig_sums(th2, C2, S2);
    bool ic = i < 32, jc = j < 32;
    double r;
    if (ic && jc)        r = 0.5 * (C1 + C2);   // cos*cos
    else if (!ic && !jc) r = 0.5 * (C1 - C2);   // sin*sin
    else if (ic && !jc)  r = 0.5 * (S2 - S1);   // cos(a s) sin(b s)
    else                 r = 0.5 * (S2 + S1);   // sin(a s) cos(b s)
    g_R[g] = (float)r;
}
__global__ void fold_wv(const float* __restrict__ Wv) {
    int g = blockIdx.x * blockDim.x + threadIdx.x;
    int j = g & 63;
    int h = (g >> 6) & (NH - 1);
    int d = g >> 10;
    const float* wrow = Wv + (size_t)d * ND + h * 64;
    float acc = 0.f;
#pragma unroll 8
    for (int i = 0; i < 64; i++)
        acc += wrow[i] * g_R[i * 64 + j];
    g_Wvp[g] = acc;
}
__global__ void prep_a(const float* __restrict__ X, __half* __restrict__ A, int n4) {
    int g = blockIdx.x * blockDim.x + threadIdx.x;
    if (g >= n4) return;
    float4 v = ((const float4*)X)[g];
    uint2 o;
    o.x = pack_f16(v.x, v.y);
    o.y = pack_f16(v.z, v.w);
    ((uint2*)A)[g] = o;
}
__global__ void prep_w4(const float* __restrict__ Wq, const float* __restrict__ Wk,
                        const float* __restrict__ Wo) {
    __shared__ float t[32][33];
    const int z = blockIdx.z;
    const float* W = (z == 0) ? Wq : (z == 1) ? Wk : (z == 2) ? g_Wvp : Wo;
    __half* dst = (z < 3) ? (g_W + (size_t)z * ND * ND) : g_WoH;
    int k0 = blockIdx.y * 32, n0 = blockIdx.x * 32;
    int tx = threadIdx.x, ty = threadIdx.y;
#pragma unroll
    for (int i = 0; i < 32; i += 8)
        t[ty + i][tx] = W[(size_t)(k0 + ty + i) * ND + n0 + tx];
    __syncthreads();
#pragma unroll
    for (int i = 0; i < 32; i += 8) {
        int n = n0 + ty + i, k = k0 + tx;
        dst[(size_t)n * ND + k] = __float2half(t[tx][ty + i]);
    }
}

// ---------------- HMMA GEMM tile: 128x128x32, 4 warps (2x2 of 64x64) --------
#define GST 10240

__device__ __noinline__ void gemm_tile(
    const __half* __restrict__ A, const __half* __restrict__ B,
    float* __restrict__ C, const float* __restrict__ bias,
    int m0, int n0, int Ncols, int epi, char* smemc)
{
    const uint32_t sbase = smem_u32(smemc);
    const int tid = threadIdx.x, lane = tid & 31, wid = tid >> 5;
    const int wm = wid >> 1, wn = wid & 1;
    const __half* Ap = A + (size_t)m0 * ND;
    const __half* Bp = B + (size_t)n0 * ND;

#define G_LOAD(st, ch)                                                        \
    do {                                                                      \
        uint32_t _sA = sbase + (st) * GST;                                    \
        uint32_t _sB = sbase + 3 * GST + (st) * GST;                          \
        const __half* _ag = Ap + (ch) * 32;                                   \
        const __half* _bg = Bp + (ch) * 32;                                   \
        _Pragma("unroll")                                                     \
        for (int _i = 0; _i < 4; _i++) {                                      \
            int _idx = _i * 128 + tid;                                        \
            int _r = _idx >> 2, _sg = _idx & 3;                               \
            uint32_t _o = (uint32_t)(_r * 80 + _sg * 16);                     \
            CPA16(_sA + _o, _ag + (size_t)_r * ND + _sg * 8);                 \
            CPA16(_sB + _o, _bg + (size_t)_r * ND + _sg * 8);                 \
        }                                                                     \
        CPCOMMIT();                                                           \
    } while (0)

    float acc[4][8][4];
#pragma unroll
    for (int i = 0; i < 4; i++)
#pragma unroll
        for (int jx = 0; jx < 8; jx++)
#pragma unroll
            for (int k = 0; k < 4; k++) acc[i][jx][k] = 0.f;

    G_LOAD(0, 0);
    G_LOAD(1, 1);

    for (int c = 0; c < NCHUNK; c++) {
        if (c < NCHUNK - 1) CPWAIT1(); else CPWAIT0();
        __syncthreads();
        if (c + 2 < NCHUNK) G_LOAD((c + 2) % 3, c + 2);

        int st = c % 3;
        uint32_t sA = sbase + st * GST;
        uint32_t sB = sbase + 3 * GST + st * GST;
#pragma unroll
        for (int kk = 0; kk < 2; kk++) {
            uint32_t a[4][4], b[8][2];
#pragma unroll
            for (int mi = 0; mi < 4; mi++) {
                uint32_t ad = sA + (uint32_t)((wm * 64 + mi * 16 + (lane & 15)) * 80
                                              + kk * 32 + (lane >> 4) * 16);
                LDSM4(a[mi], ad);
            }
#pragma unroll
            for (int pr = 0; pr < 4; pr++) {
                uint32_t t4[4];
                uint32_t bd = sB + (uint32_t)((wn * 64 + pr * 16 + ((lane >> 4) & 1) * 8
                                               + (lane & 7)) * 80
                                              + kk * 32 + ((lane >> 3) & 1) * 16);
                LDSM4(t4, bd);
                b[2 * pr][0] = t4[0]; b[2 * pr][1] = t4[1];
                b[2 * pr + 1][0] = t4[2]; b[2 * pr + 1][1] = t4[3];
            }
#pragma unroll
            for (int mi = 0; mi < 4; mi++)
#pragma unroll
                for (int ni = 0; ni < 8; ni++)
                    MMA_F16(acc[mi][ni], a[mi], b[ni]);
        }
    }
    __syncthreads();

    if (epi == 2) {
        const int arr = n0 >> 10;
        __half* hb = (arr == 0) ? g_Qs : (arr == 1) ? g_Ks : g_Vs;
        const float sc = (arr == 0) ? QSCALE : 1.f;
#pragma unroll
        for (int mi = 0; mi < 4; mi++)
#pragma unroll
            for (int ni = 0; ni < 8; ni++) {
                int row = m0 + wm * 64 + mi * 16 + (lane >> 2);
                int cc = (n0 & 1023) + wn * 64 + ni * 8 + (lane & 3) * 2;
                size_t di = (size_t)row * ND + cc;
                *(uint32_t*)&hb[di] = pack_f16(acc[mi][ni][0] * sc, acc[mi][ni][1] * sc);
                *(uint32_t*)&hb[di + (size_t)8 * ND] =
                    pack_f16(acc[mi][ni][2] * sc, acc[mi][ni][3] * sc);
            }
    } else {
#pragma unroll
        for (int mi = 0; mi < 4; mi++)
#pragma unroll
            for (int ni = 0; ni < 8; ni++) {
                int row = m0 + wm * 64 + mi * 16 + (lane >> 2);
                int col = n0 + wn * 64 + ni * 8 + (lane & 3) * 2;
                float b0 = bias[col], b1 = bias[col + 1];
                float2 v0 = { acc[mi][ni][0] + b0, acc[mi][ni][1] + b1 };
                float2 v1 = { acc[mi][ni][2] + b0, acc[mi][ni][3] + b1 };
                *(float2*)&C[(size_t)row * Ncols + col] = v0;
                *(float2*)&C[(size_t)(row + 8) * Ncols + col] = v1;
            }
    }
#undef G_LOAD
}

// ---------------- flash tile: Br=128 (4 warps), Bc=64, hd=64 ----------------
#define FQB   18432
#define FKVB  9216

__device__ __noinline__ void flash_tile(int qt, int b, int h, char* smemc)
{
    const uint32_t sbase = smem_u32(smemc);
    const uint32_t sQ = sbase;
    const uint32_t sKV0 = sbase + FQB;

    const int tid = threadIdx.x, lane = tid & 31, wid = tid >> 5;
    const int q0 = qt * 128;
    const int wq = wid * 32;
    const size_t base = ((size_t)b * NT) * ND + (size_t)h * 64;

    const __half* gs[2] = { g_Ks + base, g_Vs + base };

#define KV_LOAD(stg, kv0)                                                     \
    do {                                                                      \
        uint32_t _sd = sKV0 + (stg) * (2 * FKVB);                             \
        _Pragma("unroll")                                                     \
        for (int _i = 0; _i < 8; _i++) {                                      \
            int _idx = _i * 128 + tid;                                        \
            int _arr = _idx >> 9, _rem = _idx & 511;                          \
            int _r = _rem >> 3, _sg = _rem & 7;                               \
            CPA16(_sd + (uint32_t)(_arr * FKVB + _r * 144 + _sg * 16),        \
                  gs[_arr] + (size_t)((kv0) + _r) * ND + _sg * 8);            \
        }                                                                     \
        CPCOMMIT();                                                           \
    } while (0)

    {
        const __half* qp = g_Qs + base;
#pragma unroll
        for (int i = 0; i < 8; i++) {
            int idx = i * 128 + tid;
            int r = idx >> 3, sg = idx & 7;
            CPA16(sQ + (uint32_t)(r * 144 + sg * 16),
                  qp + (size_t)(q0 + r) * ND + sg * 8);
        }
    }
    KV_LOAD(0, 0);
    KV_LOAD(1, 64);

    CPWAIT1();
    __syncthreads();
    uint32_t aq[4][2][4];
#pragma unroll
    for (int kk = 0; kk < 4; kk++)
#pragma unroll
        for (int mi = 0; mi < 2; mi++) {
            uint32_t off = (uint32_t)((wq + mi * 16 + (lane & 15)) * 144
                                      + kk * 32 + (lane >> 4) * 16);
            LDSM4(aq[kk][mi], sQ + off);
        }

    float o[2][8][4];
    float mrow[2][2], lrow[2][2];
#pragma unroll
    for (int mi = 0; mi < 2; mi++) {
        mrow[mi][0] = mrow[mi][1] = -1e30f;
        lrow[mi][0] = lrow[mi][1] = 0.f;
#pragma unroll
        for (int nd = 0; nd < 8; nd++)
#pragma unroll
            for (int k = 0; k < 4; k++) o[mi][nd][k] = 0.f;
    }

    for (int t = 0; t < NT / 64; t++) {
        if (t < NT / 64 - 1) CPWAIT1(); else CPWAIT0();
        __syncthreads();
        const uint32_t sK = sKV0 + (t & 1) * (2 * FKVB);
        const uint32_t sV = sK + FKVB;

        float s[2][8][4];
#pragma unroll
        for (int mi = 0; mi < 2; mi++)
#pragma unroll
            for (int ni = 0; ni < 8; ni++)
#pragma unroll
                for (int k = 0; k < 4; k++) s[mi][ni][k] = 0.f;

#pragma unroll
        for (int kk = 0; kk < 4; kk++) {
            uint32_t bk[8][2];
#pragma unroll
            for (int pr = 0; pr < 4; pr++) {
                uint32_t off = (uint32_t)((pr * 16 + ((lane >> 4) & 1) * 8 + (lane & 7)) * 144
                                          + kk * 32 + ((lane >> 3) & 1) * 16);
                uint32_t t4[4];
                LDSM4(t4, sK + off);
                bk[2 * pr][0] = t4[0]; bk[2 * pr][1] = t4[1];
                bk[2 * pr + 1][0] = t4[2]; bk[2 * pr + 1][1] = t4[3];
            }
#pragma unroll
            for (int mi = 0; mi < 2; mi++)
#pragma unroll
                for (int ni = 0; ni < 8; ni++)
                    MMA_F16(s[mi][ni], aq[kk][mi], bk[ni]);
        }

#pragma unroll
        for (int mi = 0; mi < 2; mi++)
#pragma unroll
            for (int hf = 0; hf < 2; hf++) {
                float vmax = -1e30f;
#pragma unroll
                for (int ni = 0; ni < 8; ni++)
                    vmax = fmaxf(vmax, fmaxf(s[mi][ni][2 * hf], s[mi][ni][2 * hf + 1]));
                vmax = fmaxf(vmax, __shfl_xor_sync(0xffffffffu, vmax, 1));
                vmax = fmaxf(vmax, __shfl_xor_sync(0xffffffffu, vmax, 2));
                float mo = mrow[mi][hf];
                float mn = fmaxf(mo, vmax);
                float corr = ex2(mo - mn);
                mrow[mi][hf] = mn;
                float rs = 0.f;
#pragma unroll
                for (int ni = 0; ni < 8; ni++) {
                    float p0 = ex2(s[mi][ni][2 * hf] - mn);
                    float p1 = ex2(s[mi][ni][2 * hf + 1] - mn);
                    s[mi][ni][2 * hf] = p0;
                    s[mi][ni][2 * hf + 1] = p1;
                    rs += p0 + p1;
                }
                rs += __shfl_xor_sync(0xffffffffu, rs, 1);
                rs += __shfl_xor_sync(0xffffffffu, rs, 2);
                lrow[mi][hf] = lrow[mi][hf] * corr + rs;
#pragma unroll
                for (int ni = 0; ni < 8; ni++) {
                    o[mi][ni][2 * hf] *= corr;
                    o[mi][ni][2 * hf + 1] *= corr;
                }
            }

#pragma unroll
        for (int kk = 0; kk < 4; kk++) {
            uint32_t bv[8][2];
#pragma unroll
            for (int q = 0; q < 4; q++) {
                uint32_t off = (uint32_t)((kk * 16 + ((lane >> 3) & 1) * 8 + (lane & 7)) * 144
                                          + q * 32 + ((lane >> 4) & 1) * 16);
                uint32_t t4[4];
                LDSM4T(t4, sV + off);
                bv[2 * q][0] = t4[0]; bv[2 * q][1] = t4[1];
                bv[2 * q + 1][0] = t4[2]; bv[2 * q + 1][1] = t4[3];
            }
#pragma unroll
            for (int mi = 0; mi < 2; mi++) {
                const float* p0 = s[mi][2 * kk];
                const float* p1 = s[mi][2 * kk + 1];
                uint32_t ap[4];
                ap[0] = pack_f16(p0[0], p0[1]);
                ap[1] = pack_f16(p0[2], p0[3]);
                ap[2] = pack_f16(p1[0], p1[1]);
                ap[3] = pack_f16(p1[2], p1[3]);
#pragma unroll
                for (int nd = 0; nd < 8; nd++)
                    MMA_F16(o[mi][nd], ap, bv[nd]);
            }
        }

        if (t + 2 < NT / 64) {
            __syncthreads();
            KV_LOAD(t & 1, (t + 2) * 64);
        }
    }

#pragma unroll
    for (int mi = 0; mi < 2; mi++)
#pragma unroll
        for (int hf = 0; hf < 2; hf++) {
            float inv = 1.f / lrow[mi][hf];
            int m = b * NT + q0 + wq + mi * 16 + (lane >> 2) + hf * 8;
#pragma unroll
            for (int nd = 0; nd < 8; nd++) {
                int k = h * 64 + nd * 8 + (lane & 3) * 2;
                *(uint32_t*)&g_O16[(size_t)m * ND + k] =
                    pack_f16(o[mi][nd][2 * hf] * inv, o[mi][nd][2 * hf + 1] * inv);
            }
        }
#undef KV_LOAD
}

// ---------------- fused compute kernel ---------------------------------------
// bid layout: 8 head-pair groups of 160 = [96 QKV tiles | 64 flash tiles],
// then 256 out-proj tiles. QKV kinds within group: 0=K, 1=V, 2=Q.
__global__ __launch_bounds__(128, 2)
void fused(const float* __restrict__ bo, float* __restrict__ out)
{
    extern __shared__ char smemc[];
    const int bid = blockIdx.x;

    if (bid < 1280) {
        int hp = bid / 160, l = bid % 160;
        if (l < 96) {
            int kind = l >> 5, m = l & 31;
            int nt = (kind == 0) ? 8 + hp : (kind == 1) ? 16 + hp : hp;
            gemm_tile(g_A, g_W, nullptr, nullptr, m * 128, nt * 128, 0, 2, smemc);
            donecnt(nt * 2 + (m >> 4));
        } else {
            int w = l - 96;
            int h = hp * 2 + (w >> 5), b = (w >> 4) & 1, qt = w & 15;
            waitcnt(hp * 2 + b, 16);              // Q half for this batch
            waitcnt((8 + hp) * 2 + b, 16);        // K half
            waitcnt((16 + hp) * 2 + b, 16);       // V half
            flash_tile(qt, b, h, smemc);
            donecnt(C_FL + b * 16 + qt);
        }
    } else {
        int l = bid - 1280, mt = l >> 3, ntc = l & 7;
        waitcnt(C_FL + mt, 16);
        gemm_tile(g_O16, g_WoH, out, bo, mt * 128, ntc * 128, ND, 1, smemc);
    }
}

// ---------------- host launcher --------------------------------------------
extern "C" void kernel_launch(void* const* d_in, const int* in_sizes, int n_in,
                              void* d_out, int out_size) {
    (void)in_sizes; (void)n_in; (void)out_size;
    const float* x  = (const float*)d_in[0];
    const float* Wq = (const float*)d_in[1];
    const float* Wk = (const float*)d_in[2];
    const float* Wv = (const float*)d_in[3];
    const float* Wo = (const float*)d_in[4];
    const float* bo = (const float*)d_in[5];
    float* out = (float*)d_out;

    __half *Aap;
    int* syncp;
    cudaGetSymbolAddress((void**)&Aap, g_A);
    cudaGetSymbolAddress((void**)&syncp, g_sync);
    cudaMemsetAsync(syncp, 0, sizeof(int) * 96, 0);

    compute_R_closed<<<16, 256>>>();
    fold_wv<<<(ND * ND) / 256, 256>>>(Wv);
    prep_a<<<(NBT * ND / 4 + 255) / 256, 256>>>(x, Aap, NBT * ND / 4);
    prep_w4<<<dim3(32, 32, 4), dim3(32, 8)>>>(Wq, Wk, Wo);

    cudaFuncSetAttribute(fused, cudaFuncAttributeMaxDynamicSharedMemorySize, 61440);
    fused<<<1536, 128, 61440>>>(bo, out);
}